// round 2
// baseline (speedup 1.0000x reference)
#include <cuda_runtime.h>
#include <cstdint>

// Scratch: inverse permutation inv[p*load + tag] = global source row (p*T + t).
#define INV_MAX (1 << 21)
__device__ int d_inv[INV_MAX];
__device__ int d_tag_is_i32;   // 1 if tags buffer is int32, 0 if int64

__global__ void reset_flag_kernel() { d_tag_is_i32 = 0; }

// Probe dtype: read first n_half elements as int64. If tags are really int64,
// all values lie in [0, load). If the buffer is int32, the int64 view packs
// two tags per read and is out of range almost everywhere.
__global__ void detect_dtype_kernel(const long long* __restrict__ tags64,
                                    int n_half, int load) {
    int idx = blockIdx.x * blockDim.x + threadIdx.x;
    if (idx < n_half) {
        long long v = tags64[idx];
        if (v < 0 || v >= (long long)load) atomicOr(&d_tag_is_i32, 1);
    }
}

// Invert the per-flow tag permutations (dtype-aware via flag).
__global__ void invert_tags_kernel(const void* __restrict__ tags,
                                   int n, int T, int load) {
    int idx = blockIdx.x * blockDim.x + threadIdx.x;
    if (idx < n) {
        int p = idx / T;
        long long tag;
        if (d_tag_is_i32) tag = ((const int*)tags)[idx];
        else              tag = ((const long long*)tags)[idx];
        if (tag >= 0 && tag < load)
            d_inv[(long long)p * load + tag] = idx;
    }
}

// Hot kernel: out[i] = data[inv0[i]] + data[inv1[i]], float4-vectorized.
__global__ void gather_sum2_kernel(const float4* __restrict__ data,
                                   float4* __restrict__ out,
                                   int load, int Dv) {
    long long gid = (long long)blockIdx.x * blockDim.x + threadIdx.x;
    long long total = (long long)load * Dv;
    if (gid >= total) return;
    int row = (int)(gid / Dv);
    int col = (int)(gid % Dv);
    int s0 = __ldg(&d_inv[row]);
    int s1 = __ldg(&d_inv[load + row]);
    float4 a = __ldg(&data[(long long)s0 * Dv + col]);
    float4 b = __ldg(&data[(long long)s1 * Dv + col]);
    float4 r;
    r.x = a.x + b.x;
    r.y = a.y + b.y;
    r.z = a.z + b.z;
    r.w = a.w + b.w;
    out[gid] = r;
}

// Generic-P fallback.
__global__ void gather_sumP_kernel(const float4* __restrict__ data,
                                   float4* __restrict__ out,
                                   int load, int Dv, int P) {
    long long gid = (long long)blockIdx.x * blockDim.x + threadIdx.x;
    long long total = (long long)load * Dv;
    if (gid >= total) return;
    int row = (int)(gid / Dv);
    int col = (int)(gid % Dv);
    float4 r = make_float4(0.f, 0.f, 0.f, 0.f);
    for (int p = 0; p < P; ++p) {
        int s = __ldg(&d_inv[(long long)p * load + row]);
        float4 v = __ldg(&data[(long long)s * Dv + col]);
        r.x += v.x; r.y += v.y; r.z += v.z; r.w += v.w;
    }
    out[gid] = r;
}

// Scalar fallback if D % 4 != 0.
__global__ void gather_sumP_scalar_kernel(const float* __restrict__ data,
                                          float* __restrict__ out,
                                          int load, int D, int P) {
    long long gid = (long long)blockIdx.x * blockDim.x + threadIdx.x;
    long long total = (long long)load * D;
    if (gid >= total) return;
    int row = (int)(gid / D);
    int col = (int)(gid % D);
    float r = 0.f;
    for (int p = 0; p < P; ++p) {
        int s = __ldg(&d_inv[(long long)p * load + row]);
        r += __ldg(&data[(long long)s * D + col]);
    }
    out[gid] = r;
}

extern "C" void kernel_launch(void* const* d_in, const int* in_sizes, int n_in,
                              void* d_out, int out_size) {
    const float* flows_data = (const float*)d_in[0];
    const void* flows_tag = d_in[1];

    int n_rows = in_sizes[1];            // P * T
    int D = in_sizes[0] / n_rows;        // feature dim
    int load = out_size / D;             // output rows (== T here)
    int P = n_rows / load;               // paths (== 2 here)
    int T = n_rows / P;                  // tokens per flow

    // Prologue: dtype probe + inverse permutation (tiny).
    reset_flag_kernel<<<1, 1>>>();
    {
        int n_half = n_rows / 2;         // safe to read as int64 even if int32
        int threads = 256;
        int blocks = (n_half + threads - 1) / threads;
        if (blocks > 0)
            detect_dtype_kernel<<<blocks, threads>>>(
                (const long long*)flows_tag, n_half, load);
    }
    {
        int threads = 256;
        int blocks = (n_rows + threads - 1) / threads;
        invert_tags_kernel<<<blocks, threads>>>(flows_tag, n_rows, T, load);
    }

    // Hot gather-sum (HBM-bound).
    if ((D & 3) == 0) {
        int Dv = D >> 2;
        long long total = (long long)load * Dv;
        int threads = 256;
        long long blocks = (total + threads - 1) / threads;
        if (P == 2) {
            gather_sum2_kernel<<<(unsigned)blocks, threads>>>(
                (const float4*)flows_data, (float4*)d_out, load, Dv);
        } else {
            gather_sumP_kernel<<<(unsigned)blocks, threads>>>(
                (const float4*)flows_data, (float4*)d_out, load, Dv, P);
        }
    } else {
        long long total = (long long)load * D;
        int threads = 256;
        long long blocks = (total + threads - 1) / threads;
        gather_sumP_scalar_kernel<<<(unsigned)blocks, threads>>>(
            flows_data, (float*)d_out, load, D, P);
    }
}

// round 3
// speedup vs baseline: 1.2353x; 1.2353x over previous
#include <cuda_runtime.h>
#include <cstdint>

// Scratch: inverse permutation inv[p*load + tag] = global source row (p*T + t).
#define INV_MAX (1 << 21)
__device__ int d_inv[INV_MAX];

// Fused dtype-probe + permutation inversion.
// Probe: read the first min(n/2, 64) elements through an int64 view. If tags
// are genuinely int64, every value lies in [0, load). If the buffer is int32,
// those reads pack pairs (lo=tags[2i], hi=tags[2i+1]); the first 128 tags of
// flow 0 are a permutation slice containing at most one zero, so >=63 of the
// 64 high words are nonzero -> value >= 2^32 -> out of range -> detected.
// Every block computes the identical verdict locally (deterministic, no
// global flag, no extra launches).
__global__ void invert_fused_kernel(const void* __restrict__ tags,
                                    int n, int T, int load) {
    __shared__ int s_is32;
    if (threadIdx.x == 0) s_is32 = 0;
    __syncthreads();
    int scan = n / 2 < 64 ? n / 2 : 64;
    if ((int)threadIdx.x < scan) {
        long long v = ((const long long*)tags)[threadIdx.x];
        if (v < 0 || v >= (long long)load) atomicOr(&s_is32, 1);
    }
    __syncthreads();
    bool is32 = (s_is32 != 0);

    int stride = gridDim.x * blockDim.x;
    for (int idx = blockIdx.x * blockDim.x + threadIdx.x; idx < n; idx += stride) {
        int p = idx / T;
        long long tag = is32 ? (long long)((const int*)tags)[idx]
                             : ((const long long*)tags)[idx];
        if (tag >= 0 && tag < (long long)load)
            d_inv[(long long)p * load + tag] = idx;
    }
}

// Hot kernel, P=2: block per output row. Indices loaded once (warp broadcast),
// columns swept coalesced with 2x unroll for MLP; streaming cache hints.
__global__ void __launch_bounds__(256) gather_row2_kernel(
    const float4* __restrict__ data, float4* __restrict__ out, int load, int Dv) {
    int row = blockIdx.x;
    int s0 = __ldg(&d_inv[row]);
    int s1 = __ldg(&d_inv[load + row]);
    const float4* __restrict__ a = data + (long long)s0 * Dv;
    const float4* __restrict__ b = data + (long long)s1 * Dv;
    float4* __restrict__ o = out + (long long)row * Dv;

    int c = threadIdx.x;
    int step = blockDim.x;
    // Unrolled-by-2 main loop: 4 independent loads in flight.
    for (; c + step < Dv; c += 2 * step) {
        float4 a0 = __ldcs(a + c);
        float4 b0 = __ldcs(b + c);
        float4 a1 = __ldcs(a + c + step);
        float4 b1 = __ldcs(b + c + step);
        float4 r0, r1;
        r0.x = a0.x + b0.x; r0.y = a0.y + b0.y; r0.z = a0.z + b0.z; r0.w = a0.w + b0.w;
        r1.x = a1.x + b1.x; r1.y = a1.y + b1.y; r1.z = a1.z + b1.z; r1.w = a1.w + b1.w;
        __stcs(o + c, r0);
        __stcs(o + c + step, r1);
    }
    if (c < Dv) {
        float4 a0 = __ldcs(a + c);
        float4 b0 = __ldcs(b + c);
        float4 r0;
        r0.x = a0.x + b0.x; r0.y = a0.y + b0.y; r0.z = a0.z + b0.z; r0.w = a0.w + b0.w;
        __stcs(o + c, r0);
    }
}

// Generic-P fallback: block per output row, accumulate over P flows.
__global__ void __launch_bounds__(256) gather_rowP_kernel(
    const float4* __restrict__ data, float4* __restrict__ out,
    int load, int Dv, int P) {
    int row = blockIdx.x;
    float4* __restrict__ o = out + (long long)row * Dv;
    for (int c = threadIdx.x; c < Dv; c += blockDim.x) {
        float4 r = make_float4(0.f, 0.f, 0.f, 0.f);
        for (int p = 0; p < P; ++p) {
            int s = __ldg(&d_inv[(long long)p * load + row]);
            float4 v = __ldcs(data + (long long)s * Dv + c);
            r.x += v.x; r.y += v.y; r.z += v.z; r.w += v.w;
        }
        __stcs(o + c, r);
    }
}

// Scalar fallback if D % 4 != 0.
__global__ void gather_rowP_scalar_kernel(
    const float* __restrict__ data, float* __restrict__ out,
    int load, int D, int P) {
    int row = blockIdx.x;
    float* __restrict__ o = out + (long long)row * D;
    for (int c = threadIdx.x; c < D; c += blockDim.x) {
        float r = 0.f;
        for (int p = 0; p < P; ++p) {
            int s = __ldg(&d_inv[(long long)p * load + row]);
            r += __ldg(data + (long long)s * D + c);
        }
        o[c] = r;
    }
}

extern "C" void kernel_launch(void* const* d_in, const int* in_sizes, int n_in,
                              void* d_out, int out_size) {
    const float* flows_data = (const float*)d_in[0];
    const void* flows_tag = d_in[1];

    int n_rows = in_sizes[1];            // P * T
    int D = in_sizes[0] / n_rows;        // feature dim
    int load = out_size / D;             // output rows (== T here)
    int P = n_rows / load;               // paths (== 2 here)
    int T = n_rows / P;                  // tokens per flow

    // Prologue: single fused probe+invert launch (tiny).
    {
        int threads = 256;
        int blocks = (n_rows + threads - 1) / threads;
        if (blocks > 64) blocks = 64;
        invert_fused_kernel<<<blocks, threads>>>(flows_tag, n_rows, T, load);
    }

    // Hot gather-sum: block per output row.
    if ((D & 3) == 0) {
        int Dv = D >> 2;
        if (P == 2) {
            gather_row2_kernel<<<load, 256>>>(
                (const float4*)flows_data, (float4*)d_out, load, Dv);
        } else {
            gather_rowP_kernel<<<load, 256>>>(
                (const float4*)flows_data, (float4*)d_out, load, Dv, P);
        }
    } else {
        gather_rowP_scalar_kernel<<<load, 256>>>(
            flows_data, (float*)d_out, load, D, P);
    }
}